// round 14
// baseline (speedup 1.0000x reference)
#include <cuda_runtime.h>
#include <cstdint>

#define BATCH 4
#define SEQLEN 4096
#define DMODEL 1024
#define DSTATE 16
#define NROWS (BATCH*SEQLEN)
#define NCHUNK 256                // 16-row chunks per sequence

// Scratch in [b][s][n] layout
__device__ float g_bx[NROWS*DSTATE];
__device__ float g_decay[NROWS*DSTATE];
__device__ float g_cA[BATCH*DSTATE*NCHUNK];
__device__ float g_cH[BATCH*DSTATE*NCHUNK];
__device__ float g_hpre[BATCH*DSTATE*NCHUNK];

// ---- packed f32x2 helpers ---------------------------------------------------
__device__ __forceinline__ double pk2(float lo, float hi) {
    double d; asm("mov.b64 %0, {%1, %2};" : "=d"(d) : "f"(lo), "f"(hi)); return d;
}
__device__ __forceinline__ double fma2(double a, double b, double c) {
    double d; asm("fma.rn.f32x2 %0, %1, %2, %3;" : "=d"(d) : "d"(a), "d"(b), "d"(c)); return d;
}
__device__ __forceinline__ double mul2(double a, double b) {
    double d; asm("mul.rn.f32x2 %0, %1, %2;" : "=d"(d) : "d"(a), "d"(b)); return d;
}
__device__ __forceinline__ double add2(double a, double b) {
    double d; asm("add.rn.f32x2 %0, %1, %2;" : "=d"(d) : "d"(a), "d"(b)); return d;
}
__device__ __forceinline__ float lo2(double d) { return __int_as_float(__double2loint(d)); }
__device__ __forceinline__ float hi2(double d) { return __int_as_float(__double2hiint(d)); }
__device__ __forceinline__ void stcs2(void* p, double a, double b) {
    asm volatile("st.global.cs.v2.f64 [%0], {%1, %2};" :: "l"(p), "d"(a), "d"(b) : "memory");
}

// ---------------------------------------------------------------------------
// Kernel 1: Bx = x @ B_in ; decay = exp(softplus(Bx) * -exp(A))
// S-SPLIT: 512 blocks x 32 rows, 256 threads. Thread (c=t&15, rgrp=(t>>4)&7,
// sgrp=t>>7) owns 4 rows x 4 s-pairs (s-half sgrp). Doubles total warps vs
// R12 (13.8 -> 27.7 warps/SM) at the same B-LDS traffic; the second s-group's
// x loads are L1 hits. B staged pitch 18 (proven conflict-free LDS.64),
// 2-deep x prefetch. Emits two 16-row chunk summaries per block.
// ---------------------------------------------------------------------------
__global__ __launch_bounds__(256, 3) void bx_kernel(const float* __restrict__ x,
                                                    const float* __restrict__ A,
                                                    const float* __restrict__ B_in) {
    __shared__ __align__(16) float sb[512 * 18];   // 36 KB
    __shared__ double sdump[32][8];
    __shared__ float sdec[DSTATE][33];
    __shared__ float sbxs[DSTATE][33];

    const int t = threadIdx.x;
    const int c = t & 15;
    const int rgrp = (t >> 4) & 7;
    const int sgrp = t >> 7;                       // 0 or 1: s-half
    const int row0 = blockIdx.x * 32 + rgrp * 4;

    double acc[4][4];
#pragma unroll
    for (int r = 0; r < 4; r++)
#pragma unroll
        for (int j = 0; j < 4; j++) acc[r][j] = 0.0;

    for (int stage = 0; stage < 2; stage++) {
        __syncthreads();
        // stage B rows [stage*512, +512) -> sb pitch 18 (double-pair stores)
        const float4* bsrc = (const float4*)(B_in + (size_t)stage * 512 * DSTATE);
#pragma unroll
        for (int i = 0; i < 8; i++) {
            int idx = i * 256 + t;                 // float4 unit 0..2047
            int e = idx >> 2, u = idx & 3;
            float4 v = bsrc[idx];
            double* dst = (double*)(sb + e * 18 + u * 4);
            dst[0] = ((const double*)&v)[0];
            dst[1] = ((const double*)&v)[1];
        }
        __syncthreads();

        const float* xp = x + (size_t)row0 * DMODEL + stage * 512 + c;
        float p0[4], p1[4];
#pragma unroll
        for (int r = 0; r < 4; r++) {
            p0[r] = xp[r * DMODEL];
            p1[r] = xp[r * DMODEL + 16];
        }

#pragma unroll 8
        for (int k = 0; k < 32; k++) {
            float cx[4];
#pragma unroll
            for (int r = 0; r < 4; r++) { cx[r] = p0[r]; p0[r] = p1[r]; }
            if (k < 30) {
#pragma unroll
                for (int r = 0; r < 4; r++) p1[r] = xp[r * DMODEL + (k + 2) * 16];
            }
            double xx[4];
#pragma unroll
            for (int r = 0; r < 4; r++) xx[r] = pk2(cx[r], cx[r]);

            const double* bp = (const double*)(sb + (c + 16 * k) * 18) + 4 * sgrp;
            double bv[4];
#pragma unroll
            for (int j = 0; j < 4; j++) bv[j] = bp[j];
#pragma unroll
            for (int r = 0; r < 4; r++)
#pragma unroll
                for (int j = 0; j < 4; j++)
                    acc[r][j] = fma2(xx[r], bv[j], acc[r][j]);
        }
    }

    // reduce across the 16 c-lanes (xor flips c bits only)
#pragma unroll
    for (int off = 1; off < 16; off <<= 1) {
#pragma unroll
        for (int r = 0; r < 4; r++)
#pragma unroll
            for (int j = 0; j < 4; j++) {
                double o = __shfl_xor_sync(0xffffffffu, acc[r][j], off);
                acc[r][j] = add2(acc[r][j], o);
            }
    }

    __syncthreads();
    if (c == 0) {
#pragma unroll
        for (int r = 0; r < 4; r++)
#pragma unroll
            for (int j = 0; j < 4; j++) sdump[rgrp * 4 + r][sgrp * 4 + j] = acc[r][j];
    }
    __syncthreads();

    // softplus/exp: 256 items (32 rows x 8 pairs), 1 per thread
    {
        const int rl = t >> 3, q = t & 7;
        const double v = sdump[rl][q];
        const float bx0 = lo2(v), bx1 = hi2(v);
        const int s0 = 2 * q;
        const float an0 = -expf(A[s0]);
        const float an1 = -expf(A[s0 + 1]);
        const float sp0 = (bx0 > 20.f) ? bx0 : log1pf(expf(bx0));
        const float sp1 = (bx1 > 20.f) ? bx1 : log1pf(expf(bx1));
        sdec[s0][rl] = expf(sp0 * an0);
        sdec[s0 + 1][rl] = expf(sp1 * an1);
        sbxs[s0][rl] = bx0;
        sbxs[s0 + 1][rl] = bx1;
    }
    __syncthreads();

    const int b = blockIdx.x >> 7;
    const int n0 = (blockIdx.x * 32) & (SEQLEN - 1);
    // coalesced global writes in [b][s][n]: 512 items, 2 per thread
#pragma unroll
    for (int i = 0; i < 2; i++) {
        int idx = i * 256 + t;
        int s = idx >> 5, j = idx & 31;
        size_t o = ((size_t)(b * DSTATE + s)) * SEQLEN + n0 + j;
        g_bx[o] = sbxs[s][j];
        g_decay[o] = sdec[s][j];
    }
    // two 16-row chunk summaries per block
    if (t < 32) {
        const int s = t & 15, half = t >> 4;
        float a = 1.f, h = 0.f;
#pragma unroll
        for (int j = 0; j < 16; j++) {
            const int jj = half * 16 + j;
            const float d = sdec[s][jj];
            h = fmaf(h, d, sbxs[s][jj]);
            a *= d;
        }
        const int so = (b * DSTATE + s) * NCHUNK + (blockIdx.x & 127) * 2 + half;
        g_cA[so] = a;
        g_cH[so] = h;
    }
}

// ---------------------------------------------------------------------------
// Kernel 2: scan 256 chunk summaries per (b,s); write EXCLUSIVE prefix.
// ---------------------------------------------------------------------------
__global__ __launch_bounds__(256) void chunkscan_kernel() {
    __shared__ float sA[256], sH[256];
    const int t = threadIdx.x;
    const int seq = blockIdx.x;                    // b*16 + s
    float a = g_cA[seq * NCHUNK + t];
    float h = g_cH[seq * NCHUNK + t];
    sA[t] = a; sH[t] = h;
    __syncthreads();
#pragma unroll
    for (int off = 1; off < 256; off <<= 1) {
        float pa = 1.f, ph = 0.f;
        const bool act = (t >= off);
        if (act) { pa = sA[t - off]; ph = sH[t - off]; }
        __syncthreads();
        if (act) {
            h = fmaf(a, ph, h);
            a = a * pa;
            sA[t] = a; sH[t] = h;
        }
        __syncthreads();
    }
    g_hpre[seq * NCHUNK + t] = (t == 0) ? 0.f : sH[t - 1];
}

// ---------------------------------------------------------------------------
// Kernel 3: replay 16-row chunk + y = hs@C + x*D.   (R12 version verbatim)
// 2048 blocks x (16 rows x 512 cols), 128 threads; thread owns 4 cols.
// Even/odd split accumulators; x loaded only if D slice != 0.
// ---------------------------------------------------------------------------
__global__ __launch_bounds__(128, 4) void out_kernel(const float* __restrict__ x,
                                                     const float* __restrict__ C,
                                                     const float* __restrict__ D,
                                                     float* __restrict__ y) {
    __shared__ float sd[DSTATE][17], sv[DSTATE][17];
    __shared__ __align__(16) double hd[16][16];    // (h,h) pairs, [row][s]
    const int t = threadIdx.x;
    const int rb = blockIdx.x >> 1;
    const int half = blockIdx.x & 1;
    const int row0 = rb * 16;
    const int b = rb >> 8, n0 = row0 & (SEQLEN - 1);
    const int chunk = rb & 255;
    const int c0 = half * 512 + 4 * t;

    // stage decay/bx tiles [16 s][16 n]
#pragma unroll
    for (int i = 0; i < 2; i++) {
        const int idx = i * 128 + t;
        const int s = idx >> 4, j = idx & 15;
        const size_t o = ((size_t)(b * DSTATE + s)) * SEQLEN + n0 + j;
        sd[s][j] = g_decay[o];
        sv[s][j] = g_bx[o];
    }
    __syncthreads();

    // replay this 16-row chunk from the precomputed exclusive prefix
    if (t < DSTATE) {
        float h = g_hpre[(b * DSTATE + t) * NCHUNK + chunk];
#pragma unroll
        for (int j = 0; j < 16; j++) {
            h = fmaf(h, sd[t][j], sv[t][j]);
            hd[j][t] = pk2(h, h);
        }
    }
    __syncthreads();

    // C columns [c0, c0+4) as natural packed doubles
    double cd0[16], cd1[16];
#pragma unroll
    for (int s = 0; s < 16; s++) {
        const double2 cv = *(const double2*)(C + (size_t)s * DMODEL + c0);
        cd0[s] = cv.x;
        cd1[s] = cv.y;
    }
    const float4 dv = *(const float4*)(D + c0);
    const bool needx = (dv.x != 0.f) || (dv.y != 0.f) || (dv.z != 0.f) || (dv.w != 0.f);
    const double dd0 = pk2(dv.x, dv.y), dd1 = pk2(dv.z, dv.w);

    const float* xrow = x + (size_t)row0 * DMODEL + c0;
    float* yrow = y + (size_t)row0 * DMODEL + c0;

    double2 nx[4];
    if (needx) {
#pragma unroll
        for (int i = 0; i < 4; i++)
            nx[i] = *(const double2*)(xrow + (size_t)i * DMODEL);
    }

#pragma unroll
    for (int r = 0; r < 16; r++) {
        double a0e, a1e;
        double a0o = 0.0, a1o = 0.0;
        if (needx) {
            const double2 cx = nx[r & 3];
            if (r + 4 < 16)
                nx[r & 3] = *(const double2*)(xrow + (size_t)(r + 4) * DMODEL);
            a0e = mul2(cx.x, dd0);
            a1e = mul2(cx.y, dd1);
        } else {
            a0e = 0.0; a1e = 0.0;
        }
#pragma unroll
        for (int q = 0; q < 4; q++) {
            const double2 h2a = *(const double2*)&hd[r][4 * q];
            const double2 h2b = *(const double2*)&hd[r][4 * q + 2];
            a0e = fma2(h2a.x, cd0[4 * q], a0e);
            a1e = fma2(h2a.x, cd1[4 * q], a1e);
            a0o = fma2(h2a.y, cd0[4 * q + 1], a0o);
            a1o = fma2(h2a.y, cd1[4 * q + 1], a1o);
            a0e = fma2(h2b.x, cd0[4 * q + 2], a0e);
            a1e = fma2(h2b.x, cd1[4 * q + 2], a1e);
            a0o = fma2(h2b.y, cd0[4 * q + 3], a0o);
            a1o = fma2(h2b.y, cd1[4 * q + 3], a1o);
        }
        stcs2(yrow + (size_t)r * DMODEL, add2(a0e, a0o), add2(a1e, a1o));
    }
}

extern "C" void kernel_launch(void* const* d_in, const int* in_sizes, int n_in,
                              void* d_out, int out_size) {
    const float* x    = (const float*)d_in[0];   // [4,4096,1024]
    const float* A    = (const float*)d_in[1];   // [1,16]
    const float* B_in = (const float*)d_in[2];   // [1024,16]
    const float* C    = (const float*)d_in[3];   // [16,1024]
    const float* D    = (const float*)d_in[4];   // [1024]
    float* y = (float*)d_out;                    // [4,4096,1024]

    bx_kernel<<<512, 256>>>(x, A, B_in);
    chunkscan_kernel<<<64, 256>>>();
    out_kernel<<<2048, 128>>>(x, C, D, y);
}

// round 16
// speedup vs baseline: 1.5180x; 1.5180x over previous
#include <cuda_runtime.h>
#include <cstdint>

#define BATCH 4
#define SEQLEN 4096
#define DMODEL 1024
#define DSTATE 16
#define NROWS (BATCH*SEQLEN)
#define NCHUNK 256                // 16-row chunks per sequence

// Scratch in [b][s][n] layout
__device__ float g_bx[NROWS*DSTATE];
__device__ float g_decay[NROWS*DSTATE];
__device__ float g_cA[BATCH*DSTATE*NCHUNK];
__device__ float g_cH[BATCH*DSTATE*NCHUNK];
__device__ float g_hpre[BATCH*DSTATE*NCHUNK];

// ---- packed f32x2 helpers ---------------------------------------------------
__device__ __forceinline__ double pk2(float lo, float hi) {
    double d; asm("mov.b64 %0, {%1, %2};" : "=d"(d) : "f"(lo), "f"(hi)); return d;
}
__device__ __forceinline__ double fma2(double a, double b, double c) {
    double d; asm("fma.rn.f32x2 %0, %1, %2, %3;" : "=d"(d) : "d"(a), "d"(b), "d"(c)); return d;
}
__device__ __forceinline__ double mul2(double a, double b) {
    double d; asm("mul.rn.f32x2 %0, %1, %2;" : "=d"(d) : "d"(a), "d"(b)); return d;
}
__device__ __forceinline__ double add2(double a, double b) {
    double d; asm("add.rn.f32x2 %0, %1, %2;" : "=d"(d) : "d"(a), "d"(b)); return d;
}
__device__ __forceinline__ float lo2(double d) { return __int_as_float(__double2loint(d)); }
__device__ __forceinline__ float hi2(double d) { return __int_as_float(__double2hiint(d)); }
__device__ __forceinline__ void stcs2(void* p, double a, double b) {
    asm volatile("st.global.cs.v2.f64 [%0], {%1, %2};" :: "l"(p), "d"(a), "d"(b) : "memory");
}

// ---- tensor-core helpers ----------------------------------------------------
__device__ __forceinline__ void mma_tf32(float& c0, float& c1, float& c2, float& c3,
                                         uint32_t a0, uint32_t a1, uint32_t a2, uint32_t a3,
                                         uint32_t b0, uint32_t b1) {
    asm volatile(
        "mma.sync.aligned.m16n8k8.row.col.f32.tf32.tf32.f32 "
        "{%0,%1,%2,%3}, {%4,%5,%6,%7}, {%8,%9}, {%0,%1,%2,%3};"
        : "+f"(c0), "+f"(c1), "+f"(c2), "+f"(c3)
        : "r"(a0), "r"(a1), "r"(a2), "r"(a3), "r"(b0), "r"(b1));
}
__device__ __forceinline__ uint32_t tf32_hi(float v) {
    return __float_as_uint(v) & 0xFFFFE000u;
}
__device__ __forceinline__ uint32_t tf32_lo(float v, uint32_t hi) {
    return __float_as_uint(v - __uint_as_float(hi));
}
__device__ __forceinline__ void cp16(uint32_t dst_smem, const void* src) {
    asm volatile("cp.async.ca.shared.global [%0], [%1], 16;" :: "r"(dst_smem), "l"(src));
}

// ---------------------------------------------------------------------------
// Kernel 1 (tensor-core): Bx = x @ B_in ; decay = exp(softplus(Bx)*-exp(A))
// 256 blocks x 64 rows, 128 threads (4 warps; warp w = rows w*16..+16).
// 3xTF32 split mma (hi*hi + lo*hi + hi*lo) -> fp32-grade precision.
// x streamed via cp.async in 32-k tiles, ring of 4 (x pitch 36, B pitch 24:
// both fragment-load patterns bank-conflict-free). Epilogue: softplus/exp,
// transpose to [b][s][n], four 16-row chunk summaries.
// ---------------------------------------------------------------------------
__global__ __launch_bounds__(128) void bx_kernel(const float* __restrict__ x,
                                                 const float* __restrict__ A,
                                                 const float* __restrict__ B_in) {
    __shared__ __align__(16) float pool[12288];    // 48 KB: 4 ring buffers of 3072
    // buffer b: x tile [64 rows][pitch 36] at pool+b*3072 (2304 floats)
    //           B tile [32 k][pitch 24]    at pool+b*3072+2304 (768 floats)
    const int t = threadIdx.x;
    const int w = t >> 5, lane = t & 31;
    const int g = lane >> 2, tg = lane & 3;
    const int row0 = blockIdx.x * 64;

    float acc[2][4];
#pragma unroll
    for (int nh = 0; nh < 2; nh++)
#pragma unroll
        for (int i = 0; i < 4; i++) acc[nh][i] = 0.f;

    const uint32_t pool_s = (uint32_t)__cvta_generic_to_shared(pool);

    // per-thread staging coords
    const int xrow0 = t >> 3, xu = t & 7;          // x: idx = j*128+t -> row=idx>>3
    const int bk = t >> 2, bu = t & 3;             // B: one f4 per thread

    // ---- issue tile kt into buffer buf ----
    auto issue = [&](int kt, int buf) {
        const uint32_t xb = pool_s + (uint32_t)(buf * 3072) * 4u;
        const uint32_t bb = xb + 2304u * 4u;
#pragma unroll
        for (int j = 0; j < 4; j++) {
            const int row = xrow0 + j * 16;        // idx=j*128+t: row = idx>>3 = j*16 + t>>3
            cp16(xb + (uint32_t)(row * 36 + xu * 4) * 4u,
                 x + (size_t)(row0 + row) * DMODEL + kt * 32 + xu * 4);
        }
        cp16(bb + (uint32_t)(bk * 24 + bu * 4) * 4u,
             B_in + (size_t)(kt * 32 + bk) * DSTATE + bu * 4);
        asm volatile("cp.async.commit_group;");
    };

    issue(0, 0); issue(1, 1); issue(2, 2);

    for (int kt = 0; kt < 32; kt++) {
        if (kt < 30)      asm volatile("cp.async.wait_group 2;");
        else if (kt == 30) asm volatile("cp.async.wait_group 1;");
        else               asm volatile("cp.async.wait_group 0;");
        __syncthreads();
        if (kt + 3 < 32) issue(kt + 3, (kt + 3) & 3);

        const float* xb = pool + (kt & 3) * 3072 + (w * 16) * 36;
        const float* bb = pool + (kt & 3) * 3072 + 2304;
#pragma unroll
        for (int ks = 0; ks < 4; ks++) {
            const int kc = ks * 8;
            const float a0f = xb[g * 36 + kc + tg];
            const float a1f = xb[(g + 8) * 36 + kc + tg];
            const float a2f = xb[g * 36 + kc + tg + 4];
            const float a3f = xb[(g + 8) * 36 + kc + tg + 4];
            const uint32_t ah0 = tf32_hi(a0f), ah1 = tf32_hi(a1f),
                           ah2 = tf32_hi(a2f), ah3 = tf32_hi(a3f);
            const uint32_t al0 = tf32_lo(a0f, ah0), al1 = tf32_lo(a1f, ah1),
                           al2 = tf32_lo(a2f, ah2), al3 = tf32_lo(a3f, ah3);
#pragma unroll
            for (int nh = 0; nh < 2; nh++) {
                const float b0f = bb[(kc + tg) * 24 + nh * 8 + g];
                const float b1f = bb[(kc + tg + 4) * 24 + nh * 8 + g];
                const uint32_t bh0 = tf32_hi(b0f), bh1 = tf32_hi(b1f);
                const uint32_t bl0 = tf32_lo(b0f, bh0), bl1 = tf32_lo(b1f, bh1);
                mma_tf32(acc[nh][0], acc[nh][1], acc[nh][2], acc[nh][3],
                         ah0, ah1, ah2, ah3, bh0, bh1);
                mma_tf32(acc[nh][0], acc[nh][1], acc[nh][2], acc[nh][3],
                         al0, al1, al2, al3, bh0, bh1);
                mma_tf32(acc[nh][0], acc[nh][1], acc[nh][2], acc[nh][3],
                         ah0, ah1, ah2, ah3, bl0, bl1);
            }
        }
    }
    __syncthreads();

    // epilogue overlays pool: raw[64][16] at 0, sdec[16][65] at 1024, sbxs at 2064
    float* raw  = pool;
    float* sdec = pool + 1024;
    float* sbxs = pool + 2064;

#pragma unroll
    for (int nh = 0; nh < 2; nh++) {
        const int col = nh * 8 + 2 * tg;
        raw[(w * 16 + g) * 16 + col]         = acc[nh][0];
        raw[(w * 16 + g) * 16 + col + 1]     = acc[nh][1];
        raw[(w * 16 + g + 8) * 16 + col]     = acc[nh][2];
        raw[(w * 16 + g + 8) * 16 + col + 1] = acc[nh][3];
    }
    __syncthreads();

#pragma unroll
    for (int i = 0; i < 8; i++) {
        const int idx = i * 128 + t;               // 0..1023 (64 rows x 16 s)
        const int row = idx >> 4, s = idx & 15;
        const float v = raw[row * 16 + s];
        const float an = -expf(A[s]);
        const float sp = (v > 20.f) ? v : log1pf(expf(v));
        sdec[s * 65 + row] = expf(sp * an);
        sbxs[s * 65 + row] = v;
    }
    __syncthreads();

    const int b = row0 >> 12;
    const int n0 = row0 & (SEQLEN - 1);
#pragma unroll
    for (int i = 0; i < 8; i++) {
        const int idx = i * 128 + t;               // 0..1023 (16 s x 64 n)
        const int s = idx >> 6, j = idx & 63;
        const size_t o = ((size_t)(b * DSTATE + s)) * SEQLEN + n0 + j;
        g_bx[o] = sbxs[s * 65 + j];
        g_decay[o] = sdec[s * 65 + j];
    }
    // four 16-row chunk summaries
    if (t < 64) {
        const int s = t & 15, ci = t >> 4;
        float a = 1.f, h = 0.f;
#pragma unroll
        for (int j = 0; j < 16; j++) {
            const int jj = ci * 16 + j;
            const float d = sdec[s * 65 + jj];
            h = fmaf(h, d, sbxs[s * 65 + jj]);
            a *= d;
        }
        const int so = (b * DSTATE + s) * NCHUNK + (n0 >> 4) + ci;
        g_cA[so] = a;
        g_cH[so] = h;
    }
}

// ---------------------------------------------------------------------------
// Kernel 2: scan 256 chunk summaries per (b,s); write EXCLUSIVE prefix.
// ---------------------------------------------------------------------------
__global__ __launch_bounds__(256) void chunkscan_kernel() {
    __shared__ float sA[256], sH[256];
    const int t = threadIdx.x;
    const int seq = blockIdx.x;                    // b*16 + s
    float a = g_cA[seq * NCHUNK + t];
    float h = g_cH[seq * NCHUNK + t];
    sA[t] = a; sH[t] = h;
    __syncthreads();
#pragma unroll
    for (int off = 1; off < 256; off <<= 1) {
        float pa = 1.f, ph = 0.f;
        const bool act = (t >= off);
        if (act) { pa = sA[t - off]; ph = sH[t - off]; }
        __syncthreads();
        if (act) {
            h = fmaf(a, ph, h);
            a = a * pa;
            sA[t] = a; sH[t] = h;
        }
        __syncthreads();
    }
    g_hpre[seq * NCHUNK + t] = (t == 0) ? 0.f : sH[t - 1];
}

// ---------------------------------------------------------------------------
// Kernel 3: replay 16-row chunk + y = hs@C + x*D.   (R12 version verbatim)
// ---------------------------------------------------------------------------
__global__ __launch_bounds__(128, 4) void out_kernel(const float* __restrict__ x,
                                                     const float* __restrict__ C,
                                                     const float* __restrict__ D,
                                                     float* __restrict__ y) {
    __shared__ float sd[DSTATE][17], sv[DSTATE][17];
    __shared__ __align__(16) double hd[16][16];    // (h,h) pairs, [row][s]
    const int t = threadIdx.x;
    const int rb = blockIdx.x >> 1;
    const int half = blockIdx.x & 1;
    const int row0 = rb * 16;
    const int b = rb >> 8, n0 = row0 & (SEQLEN - 1);
    const int chunk = rb & 255;
    const int c0 = half * 512 + 4 * t;

#pragma unroll
    for (int i = 0; i < 2; i++) {
        const int idx = i * 128 + t;
        const int s = idx >> 4, j = idx & 15;
        const size_t o = ((size_t)(b * DSTATE + s)) * SEQLEN + n0 + j;
        sd[s][j] = g_decay[o];
        sv[s][j] = g_bx[o];
    }
    __syncthreads();

    if (t < DSTATE) {
        float h = g_hpre[(b * DSTATE + t) * NCHUNK + chunk];
#pragma unroll
        for (int j = 0; j < 16; j++) {
            h = fmaf(h, sd[t][j], sv[t][j]);
            hd[j][t] = pk2(h, h);
        }
    }
    __syncthreads();

    double cd0[16], cd1[16];
#pragma unroll
    for (int s = 0; s < 16; s++) {
        const double2 cv = *(const double2*)(C + (size_t)s * DMODEL + c0);
        cd0[s] = cv.x;
        cd1[s] = cv.y;
    }
    const float4 dv = *(const float4*)(D + c0);
    const bool needx = (dv.x != 0.f) || (dv.y != 0.f) || (dv.z != 0.f) || (dv.w != 0.f);
    const double dd0 = pk2(dv.x, dv.y), dd1 = pk2(dv.z, dv.w);

    const float* xrow = x + (size_t)row0 * DMODEL + c0;
    float* yrow = y + (size_t)row0 * DMODEL + c0;

    double2 nx[4];
    if (needx) {
#pragma unroll
        for (int i = 0; i < 4; i++)
            nx[i] = *(const double2*)(xrow + (size_t)i * DMODEL);
    }

#pragma unroll
    for (int r = 0; r < 16; r++) {
        double a0e, a1e;
        double a0o = 0.0, a1o = 0.0;
        if (needx) {
            const double2 cx = nx[r & 3];
            if (r + 4 < 16)
                nx[r & 3] = *(const double2*)(xrow + (size_t)(r + 4) * DMODEL);
            a0e = mul2(cx.x, dd0);
            a1e = mul2(cx.y, dd1);
        } else {
            a0e = 0.0; a1e = 0.0;
        }
#pragma unroll
        for (int q = 0; q < 4; q++) {
            const double2 h2a = *(const double2*)&hd[r][4 * q];
            const double2 h2b = *(const double2*)&hd[r][4 * q + 2];
            a0e = fma2(h2a.x, cd0[4 * q], a0e);
            a1e = fma2(h2a.x, cd1[4 * q], a1e);
            a0o = fma2(h2a.y, cd0[4 * q + 1], a0o);
            a1o = fma2(h2a.y, cd1[4 * q + 1], a1o);
            a0e = fma2(h2b.x, cd0[4 * q + 2], a0e);
            a1e = fma2(h2b.x, cd1[4 * q + 2], a1e);
            a0o = fma2(h2b.y, cd0[4 * q + 3], a0o);
            a1o = fma2(h2b.y, cd1[4 * q + 3], a1o);
        }
        stcs2(yrow + (size_t)r * DMODEL, add2(a0e, a0o), add2(a1e, a1o));
    }
}

extern "C" void kernel_launch(void* const* d_in, const int* in_sizes, int n_in,
                              void* d_out, int out_size) {
    const float* x    = (const float*)d_in[0];   // [4,4096,1024]
    const float* A    = (const float*)d_in[1];   // [1,16]
    const float* B_in = (const float*)d_in[2];   // [1024,16]
    const float* C    = (const float*)d_in[3];   // [16,1024]
    const float* D    = (const float*)d_in[4];   // [1024]
    float* y = (float*)d_out;                    // [4,4096,1024]

    bx_kernel<<<256, 128>>>(x, A, B_in);
    chunkscan_kernel<<<64, 256>>>();
    out_kernel<<<2048, 128>>>(x, C, D, y);
}